// round 1
// baseline (speedup 1.0000x reference)
#include <cuda_runtime.h>
#include <stdint.h>

#define B_DIM 64
#define S_DIM 512
#define H_DIM 1024
#define L_DIM 512
#define NEG_INF_F (-1e9f)

// Scratch: scores/probs [B, L, S] fp32 = 64*512*512*4 = 67 MB (module-load allocation, allowed)
__device__ float g_scores[(size_t)B_DIM * L_DIM * S_DIM];

// ---------------------------------------------------------------------------
// Kernel 1: scores[b,l,s] = sum_h W[l,h] * X[b*512+s, h]
// Classic 128x128x8 SGEMM ("NT": both operands K-major), 256 threads, 8x8/thread
// M = L = 512, N = B*S = 32768, K = H = 1024
// ---------------------------------------------------------------------------
__global__ void __launch_bounds__(256) scores_gemm(
    const float* __restrict__ W,   // [L, H]
    const float* __restrict__ X)   // [B*S, H]
{
    __shared__ float As[8][128];
    __shared__ float Bs[8][128];

    const int tid = threadIdx.x;
    const int bm  = blockIdx.y;   // 0..3   over L
    const int bn  = blockIdx.x;   // 0..255 over B*S

    const int ldrow = tid >> 1;          // 0..127
    const int ldcol = (tid & 1) << 2;    // 0 or 4

    const float* Ap = W + (size_t)(bm * 128 + ldrow) * H_DIM + ldcol;
    const float* Bp = X + (size_t)(bn * 128 + ldrow) * H_DIM + ldcol;

    const int tx = tid & 15;   // 0..15 over N microtiles
    const int ty = tid >> 4;   // 0..15 over M microtiles

    float acc[8][8];
    #pragma unroll
    for (int i = 0; i < 8; ++i)
        #pragma unroll
        for (int j = 0; j < 8; ++j) acc[i][j] = 0.0f;

    for (int k0 = 0; k0 < H_DIM; k0 += 8) {
        float4 av = *reinterpret_cast<const float4*>(Ap + k0);
        float4 bv = *reinterpret_cast<const float4*>(Bp + k0);
        As[ldcol + 0][ldrow] = av.x; As[ldcol + 1][ldrow] = av.y;
        As[ldcol + 2][ldrow] = av.z; As[ldcol + 3][ldrow] = av.w;
        Bs[ldcol + 0][ldrow] = bv.x; Bs[ldcol + 1][ldrow] = bv.y;
        Bs[ldcol + 2][ldrow] = bv.z; Bs[ldcol + 3][ldrow] = bv.w;
        __syncthreads();

        #pragma unroll
        for (int k = 0; k < 8; ++k) {
            float4 a0 = *reinterpret_cast<const float4*>(&As[k][ty * 8]);
            float4 a1 = *reinterpret_cast<const float4*>(&As[k][ty * 8 + 4]);
            float4 b0 = *reinterpret_cast<const float4*>(&Bs[k][tx * 8]);
            float4 b1 = *reinterpret_cast<const float4*>(&Bs[k][tx * 8 + 4]);
            float af[8] = {a0.x, a0.y, a0.z, a0.w, a1.x, a1.y, a1.z, a1.w};
            float bf[8] = {b0.x, b0.y, b0.z, b0.w, b1.x, b1.y, b1.z, b1.w};
            #pragma unroll
            for (int i = 0; i < 8; ++i)
                #pragma unroll
                for (int j = 0; j < 8; ++j)
                    acc[i][j] += af[i] * bf[j];
        }
        __syncthreads();
    }

    // Write: n tile of width 128 stays within one batch (512 % 128 == 0)
    const int nbase = bn * 128 + tx * 8;
    const int b = nbase >> 9;
    const int s = nbase & 511;
    #pragma unroll
    for (int i = 0; i < 8; ++i) {
        const int l = bm * 128 + ty * 8 + i;
        float* outp = g_scores + ((size_t)b * L_DIM + l) * S_DIM + s;
        *reinterpret_cast<float4*>(outp)     = make_float4(acc[i][0], acc[i][1], acc[i][2], acc[i][3]);
        *reinterpret_cast<float4*>(outp + 4) = make_float4(acc[i][4], acc[i][5], acc[i][6], acc[i][7]);
    }
}

// ---------------------------------------------------------------------------
// Kernel 2: masked softmax over S, in place. One warp per (b,l) row.
// ---------------------------------------------------------------------------
__global__ void __launch_bounds__(256) softmax_kernel(const int* __restrict__ mask)
{
    const int row  = blockIdx.x * 8 + (threadIdx.x >> 5);  // b*512 + l
    const int lane = threadIdx.x & 31;
    const int b    = row >> 9;

    float* p = g_scores + (size_t)row * S_DIM;
    const int* mrow = mask + (size_t)b * S_DIM;

    float4 fv[4];
    float mx = -3e38f;
    #pragma unroll
    for (int c = 0; c < 4; ++c) {
        const int s = c * 128 + lane * 4;
        float4 x = *reinterpret_cast<const float4*>(p + s);
        int4 mm = *reinterpret_cast<const int4*>(mrow + s);
        x.x = (mm.x == 0) ? NEG_INF_F : x.x;
        x.y = (mm.y == 0) ? NEG_INF_F : x.y;
        x.z = (mm.z == 0) ? NEG_INF_F : x.z;
        x.w = (mm.w == 0) ? NEG_INF_F : x.w;
        fv[c] = x;
        mx = fmaxf(mx, fmaxf(fmaxf(x.x, x.y), fmaxf(x.z, x.w)));
    }
    #pragma unroll
    for (int o = 16; o > 0; o >>= 1) mx = fmaxf(mx, __shfl_xor_sync(0xffffffffu, mx, o));

    float sum = 0.0f;
    #pragma unroll
    for (int c = 0; c < 4; ++c) {
        fv[c].x = expf(fv[c].x - mx);
        fv[c].y = expf(fv[c].y - mx);
        fv[c].z = expf(fv[c].z - mx);
        fv[c].w = expf(fv[c].w - mx);
        sum += fv[c].x + fv[c].y + fv[c].z + fv[c].w;
    }
    #pragma unroll
    for (int o = 16; o > 0; o >>= 1) sum += __shfl_xor_sync(0xffffffffu, sum, o);

    const float inv = 1.0f / sum;
    #pragma unroll
    for (int c = 0; c < 4; ++c) {
        const int s = c * 128 + lane * 4;
        float4 x = fv[c];
        x.x *= inv; x.y *= inv; x.z *= inv; x.w *= inv;
        *reinterpret_cast<float4*>(p + s) = x;
    }
}

// ---------------------------------------------------------------------------
// Kernel 3: out[b,l,h] = sum_s P[b,l,s] * X[b,s,h]
// 128x128x8 SGEMM ("NN") per batch. M = L, N = H, K = S.
// ---------------------------------------------------------------------------
__global__ void __launch_bounds__(256) attend_gemm(
    const float* __restrict__ X,   // [B, S, H]
    float* __restrict__ out)       // [B, L, H]
{
    __shared__ float As[8][128];
    __shared__ float Bs[8][128];

    const int tid = threadIdx.x;
    const int bn = blockIdx.x;   // 0..7 over H
    const int bm = blockIdx.y;   // 0..3 over L
    const int b  = blockIdx.z;   // 0..63

    const float* Pb = g_scores + (size_t)b * L_DIM * S_DIM;
    const float* Xb = X        + (size_t)b * S_DIM * H_DIM;

    const int arow = tid >> 1;          // 0..127 (m)
    const int acol = (tid & 1) << 2;    // 0 or 4 (k)
    const int brow = tid >> 5;          // 0..7   (k)
    const int bcol = (tid & 31) << 2;   // 0..124 (n)

    const int tx = tid & 15;
    const int ty = tid >> 4;

    float acc[8][8];
    #pragma unroll
    for (int i = 0; i < 8; ++i)
        #pragma unroll
        for (int j = 0; j < 8; ++j) acc[i][j] = 0.0f;

    for (int k0 = 0; k0 < S_DIM; k0 += 8) {
        float4 av = *reinterpret_cast<const float4*>(
            Pb + (size_t)(bm * 128 + arow) * S_DIM + k0 + acol);
        float4 bv = *reinterpret_cast<const float4*>(
            Xb + (size_t)(k0 + brow) * H_DIM + bn * 128 + bcol);
        As[acol + 0][arow] = av.x; As[acol + 1][arow] = av.y;
        As[acol + 2][arow] = av.z; As[acol + 3][arow] = av.w;
        *reinterpret_cast<float4*>(&Bs[brow][bcol]) = bv;
        __syncthreads();

        #pragma unroll
        for (int k = 0; k < 8; ++k) {
            float4 a0 = *reinterpret_cast<const float4*>(&As[k][ty * 8]);
            float4 a1 = *reinterpret_cast<const float4*>(&As[k][ty * 8 + 4]);
            float4 b0 = *reinterpret_cast<const float4*>(&Bs[k][tx * 8]);
            float4 b1 = *reinterpret_cast<const float4*>(&Bs[k][tx * 8 + 4]);
            float af[8] = {a0.x, a0.y, a0.z, a0.w, a1.x, a1.y, a1.z, a1.w};
            float bf[8] = {b0.x, b0.y, b0.z, b0.w, b1.x, b1.y, b1.z, b1.w};
            #pragma unroll
            for (int i = 0; i < 8; ++i)
                #pragma unroll
                for (int j = 0; j < 8; ++j)
                    acc[i][j] += af[i] * bf[j];
        }
        __syncthreads();
    }

    #pragma unroll
    for (int i = 0; i < 8; ++i) {
        const int l = bm * 128 + ty * 8 + i;
        const int h = bn * 128 + tx * 8;
        float* outp = out + ((size_t)b * L_DIM + l) * H_DIM + h;
        *reinterpret_cast<float4*>(outp)     = make_float4(acc[i][0], acc[i][1], acc[i][2], acc[i][3]);
        *reinterpret_cast<float4*>(outp + 4) = make_float4(acc[i][4], acc[i][5], acc[i][6], acc[i][7]);
    }
}

// ---------------------------------------------------------------------------
// Launch
// ---------------------------------------------------------------------------
extern "C" void kernel_launch(void* const* d_in, const int* in_sizes, int n_in,
                              void* d_out, int out_size)
{
    const float* X    = (const float*)d_in[0];   // [B, S, H]
    const int*   mask = (const int*)  d_in[1];   // [B, S]
    const float* W    = (const float*)d_in[2];   // [L, H]
    float* out = (float*)d_out;                  // [B, L, H]

    scores_gemm<<<dim3(256, 4), 256>>>(W, X);
    softmax_kernel<<<(B_DIM * L_DIM) / 8, 256>>>(mask);
    attend_gemm<<<dim3(8, 4, 64), 256>>>(X, out);
}

// round 3
// speedup vs baseline: 3.1493x; 3.1493x over previous
#include <cuda_runtime.h>
#include <cuda_bf16.h>
#include <stdint.h>

#define B_DIM 64
#define S_DIM 512
#define H_DIM 1024
#define L_DIM 512
#define NEG_INF_F (-1e9f)

// ---------------------------------------------------------------------------
// Scratch (module-load allocations, allowed)
// ---------------------------------------------------------------------------
__device__ float         g_scores[(size_t)B_DIM * L_DIM * S_DIM];  // 67 MB
__device__ __nv_bfloat16 g_Xh[(size_t)B_DIM * S_DIM * H_DIM];
__device__ __nv_bfloat16 g_Xl[(size_t)B_DIM * S_DIM * H_DIM];
__device__ __nv_bfloat16 g_Wh[(size_t)L_DIM * H_DIM];
__device__ __nv_bfloat16 g_Wl[(size_t)L_DIM * H_DIM];
__device__ __nv_bfloat16 g_Ph[(size_t)B_DIM * L_DIM * S_DIM];
__device__ __nv_bfloat16 g_Pl[(size_t)B_DIM * L_DIM * S_DIM];

// ---------------------------------------------------------------------------
// Helpers
// ---------------------------------------------------------------------------
__device__ __forceinline__ uint32_t smem_u32(const void* p) {
    uint32_t a;
    asm("{ .reg .u64 t; cvta.to.shared.u64 t, %1; cvt.u32.u64 %0, t; }" : "=r"(a) : "l"(p));
    return a;
}

#define CP_ASYNC16(dst, src) \
    asm volatile("cp.async.cg.shared.global [%0], [%1], 16;" :: "r"(dst), "l"(src))
#define CP_COMMIT()  asm volatile("cp.async.commit_group;" ::: "memory")
#define CP_WAIT1()   asm volatile("cp.async.wait_group 1;" ::: "memory")

#define LDSM_X4(r0, r1, r2, r3, a) \
    asm volatile("ldmatrix.sync.aligned.m8n8.x4.shared.b16 {%0,%1,%2,%3}, [%4];" \
        : "=r"(r0), "=r"(r1), "=r"(r2), "=r"(r3) : "r"(a))
#define LDSM_X4T(r0, r1, r2, r3, a) \
    asm volatile("ldmatrix.sync.aligned.m8n8.x4.trans.shared.b16 {%0,%1,%2,%3}, [%4];" \
        : "=r"(r0), "=r"(r1), "=r"(r2), "=r"(r3) : "r"(a))

#define MMA_BF16(d, a0, a1, a2, a3, b0, b1) \
    asm volatile("mma.sync.aligned.m16n8k16.row.col.f32.bf16.bf16.f32 " \
        "{%0,%1,%2,%3},{%4,%5,%6,%7},{%8,%9},{%0,%1,%2,%3};" \
        : "+f"((d)[0]), "+f"((d)[1]), "+f"((d)[2]), "+f"((d)[3]) \
        : "r"(a0), "r"(a1), "r"(a2), "r"(a3), "r"(b0), "r"(b1))

// swizzles: 128B-row tiles (A, B K-major) and 256B-row tiles (B row-major)
#define SWZ128(o) ((o) ^ (((o) >> 3) & 0x70))
#define SWZ256(o) ((o) ^ (((o) >> 4) & 0x70))

__device__ __forceinline__ void split2(float v, __nv_bfloat16& h, __nv_bfloat16& l) {
    h = __float2bfloat16(v);
    l = __float2bfloat16(v - __bfloat162float(h));
}

// ---------------------------------------------------------------------------
// Converts: fp32 -> (hi, lo) bf16, flat, float4-vectorized
// ---------------------------------------------------------------------------
__global__ void convert_W(const float* __restrict__ W) {
    size_t i = ((size_t)blockIdx.x * 256 + threadIdx.x) * 4;
    float4 v = *reinterpret_cast<const float4*>(W + i);
    __nv_bfloat16 h0, l0, h1, l1, h2, l2, h3, l3;
    split2(v.x, h0, l0); split2(v.y, h1, l1); split2(v.z, h2, l2); split2(v.w, h3, l3);
    *reinterpret_cast<__nv_bfloat162*>(g_Wh + i)     = __nv_bfloat162{h0, h1};
    *reinterpret_cast<__nv_bfloat162*>(g_Wh + i + 2) = __nv_bfloat162{h2, h3};
    *reinterpret_cast<__nv_bfloat162*>(g_Wl + i)     = __nv_bfloat162{l0, l1};
    *reinterpret_cast<__nv_bfloat162*>(g_Wl + i + 2) = __nv_bfloat162{l2, l3};
}

__global__ void convert_X(const float* __restrict__ X) {
    size_t i = ((size_t)blockIdx.x * 256 + threadIdx.x) * 4;
    float4 v = *reinterpret_cast<const float4*>(X + i);
    __nv_bfloat16 h0, l0, h1, l1, h2, l2, h3, l3;
    split2(v.x, h0, l0); split2(v.y, h1, l1); split2(v.z, h2, l2); split2(v.w, h3, l3);
    *reinterpret_cast<__nv_bfloat162*>(g_Xh + i)     = __nv_bfloat162{h0, h1};
    *reinterpret_cast<__nv_bfloat162*>(g_Xh + i + 2) = __nv_bfloat162{h2, h3};
    *reinterpret_cast<__nv_bfloat162*>(g_Xl + i)     = __nv_bfloat162{l0, l1};
    *reinterpret_cast<__nv_bfloat162*>(g_Xl + i + 2) = __nv_bfloat162{l2, l3};
}

// ---------------------------------------------------------------------------
// bf16x3 split GEMM via mma.sync (HMMA), 128x128 tile, K-chunk 64, 8 warps.
// D[m,n] = sum_k A[m,k]*B[.,.]; A always K-major (lda = K-stride of rows).
//   B_KMAJOR=true : B[n,k] row-major (NT GEMM)  -> ldmatrix non-trans
//   B_KMAJOR=false: B[k,n] row-major (NN GEMM)  -> ldmatrix trans
// smem: 2 stages x (Ah|Al|Bh|Bl) x 16KB = 128KB dynamic.
// ---------------------------------------------------------------------------
#define GEMM_SMEM (2 * 4 * 16384)

template <bool B_KMAJOR>
__global__ void __launch_bounds__(256, 1) gemm_hmma_x3(
    const __nv_bfloat16* __restrict__ Ah, const __nv_bfloat16* __restrict__ Al,
    const __nv_bfloat16* __restrict__ Bh, const __nv_bfloat16* __restrict__ Bl,
    float* __restrict__ D,
    int lda, int ldb, int ldd, int nk,
    size_t strideA, size_t strideB, size_t strideD)
{
    extern __shared__ char smem[];
    const uint32_t sb = smem_u32(smem);
    const int tid = threadIdx.x;
    const int wid = tid >> 5, lane = tid & 31;
    const int warp_m = wid & 3, warp_n = wid >> 2;
    const int b  = blockIdx.z;
    const int m0 = blockIdx.y * 128;
    const int n0 = blockIdx.x * 128;

    const __nv_bfloat16* tAh = Ah + (size_t)b * strideA + (size_t)m0 * lda;
    const __nv_bfloat16* tAl = Al + (size_t)b * strideA + (size_t)m0 * lda;
    const __nv_bfloat16* pBh = Bh + (size_t)b * strideB;
    const __nv_bfloat16* pBl = Bl + (size_t)b * strideB;

    float acc[2][8][4];
    #pragma unroll
    for (int i = 0; i < 2; ++i)
        #pragma unroll
        for (int j = 0; j < 8; ++j)
            #pragma unroll
            for (int q = 0; q < 4; ++q) acc[i][j][q] = 0.0f;

    // ---- stage loader ----
    auto load_stage = [&](int c, int st) {
        const uint32_t base = sb + st * 65536;
        // A tiles: 128 rows x 64 k (128B rows)
        #pragma unroll
        for (int i = 0; i < 4; ++i) {
            int idx = i * 256 + tid;             // 0..1023
            int row = idx >> 3, sl = idx & 7;
            uint32_t doff = SWZ128(row * 128 + sl * 16);
            CP_ASYNC16(base + doff,         tAh + (size_t)row * lda + c * 64 + sl * 8);
            CP_ASYNC16(base + 16384 + doff, tAl + (size_t)row * lda + c * 64 + sl * 8);
        }
        if (B_KMAJOR) {
            const __nv_bfloat16* tBh = pBh + (size_t)n0 * ldb;
            const __nv_bfloat16* tBl = pBl + (size_t)n0 * ldb;
            #pragma unroll
            for (int i = 0; i < 4; ++i) {
                int idx = i * 256 + tid;
                int row = idx >> 3, sl = idx & 7;
                uint32_t doff = SWZ128(row * 128 + sl * 16);
                CP_ASYNC16(base + 32768 + doff, tBh + (size_t)row * ldb + c * 64 + sl * 8);
                CP_ASYNC16(base + 49152 + doff, tBl + (size_t)row * ldb + c * 64 + sl * 8);
            }
        } else {
            // B tiles: 64 k-rows x 128 n (256B rows)
            #pragma unroll
            for (int i = 0; i < 4; ++i) {
                int idx = i * 256 + tid;
                int row = idx >> 4, sl = idx & 15;
                uint32_t doff = SWZ256(row * 256 + sl * 16);
                CP_ASYNC16(base + 32768 + doff, pBh + (size_t)(c * 64 + row) * ldb + n0 + sl * 8);
                CP_ASYNC16(base + 49152 + doff, pBl + (size_t)(c * 64 + row) * ldb + n0 + sl * 8);
            }
        }
        CP_COMMIT();
    };

    load_stage(0, 0);

    for (int c = 0; c < nk; ++c) {
        if (c + 1 < nk) load_stage(c + 1, (c + 1) & 1);
        else            CP_COMMIT();     // empty group so WAIT1 drains stage c
        CP_WAIT1();
        __syncthreads();

        const uint32_t base = sb + (c & 1) * 65536;
        const uint32_t sAh = base, sAl = base + 16384;
        const uint32_t sBh = base + 32768, sBl = base + 49152;

        #pragma unroll
        for (int ks = 0; ks < 4; ++ks) {
            // A fragments: 2 m-tiles x {h,l}
            uint32_t ah[2][4], al[2][4];
            #pragma unroll
            for (int mt = 0; mt < 2; ++mt) {
                int row = warp_m * 32 + mt * 16 + (lane & 15);
                uint32_t off = SWZ128(row * 128 + ks * 32 + ((lane >> 4) << 4));
                LDSM_X4(ah[mt][0], ah[mt][1], ah[mt][2], ah[mt][3], sAh + off);
                LDSM_X4(al[mt][0], al[mt][1], al[mt][2], al[mt][3], sAl + off);
            }
            // B fragments: 8 n8-tiles x {h,l}
            uint32_t bh[8][2], bl[8][2];
            #pragma unroll
            for (int nt2 = 0; nt2 < 4; ++nt2) {
                uint32_t off;
                if (B_KMAJOR) {
                    int row = warp_n * 64 + nt2 * 16 + ((lane >> 4) << 3) + (lane & 7);
                    off = SWZ128(row * 128 + ks * 32 + (((lane >> 3) & 1) << 4));
                    LDSM_X4(bh[2 * nt2][0], bh[2 * nt2][1], bh[2 * nt2 + 1][0], bh[2 * nt2 + 1][1], sBh + off);
                    LDSM_X4(bl[2 * nt2][0], bl[2 * nt2][1], bl[2 * nt2 + 1][0], bl[2 * nt2 + 1][1], sBl + off);
                } else {
                    int krow = ks * 16 + (((lane >> 3) & 1) << 3) + (lane & 7);
                    int col  = warp_n * 64 + nt2 * 16 + ((lane >> 4) << 3);
                    off = SWZ256(krow * 256 + col * 2);
                    LDSM_X4T(bh[2 * nt2][0], bh[2 * nt2][1], bh[2 * nt2 + 1][0], bh[2 * nt2 + 1][1], sBh + off);
                    LDSM_X4T(bl[2 * nt2][0], bl[2 * nt2][1], bl[2 * nt2 + 1][0], bl[2 * nt2 + 1][1], sBl + off);
                }
            }
            // 3 products
            #pragma unroll
            for (int mt = 0; mt < 2; ++mt)
                #pragma unroll
                for (int nt = 0; nt < 8; ++nt) {
                    MMA_BF16(acc[mt][nt], ah[mt][0], ah[mt][1], ah[mt][2], ah[mt][3], bh[nt][0], bh[nt][1]);
                    MMA_BF16(acc[mt][nt], ah[mt][0], ah[mt][1], ah[mt][2], ah[mt][3], bl[nt][0], bl[nt][1]);
                    MMA_BF16(acc[mt][nt], al[mt][0], al[mt][1], al[mt][2], al[mt][3], bh[nt][0], bh[nt][1]);
                }
        }
        __syncthreads();
    }

    // epilogue
    float* Db = D + (size_t)b * strideD;
    #pragma unroll
    for (int mt = 0; mt < 2; ++mt) {
        int row = m0 + warp_m * 32 + mt * 16 + (lane >> 2);
        #pragma unroll
        for (int nt = 0; nt < 8; ++nt) {
            int col = n0 + warp_n * 64 + nt * 8 + (lane & 3) * 2;
            *reinterpret_cast<float2*>(Db + (size_t)row * ldd + col) =
                make_float2(acc[mt][nt][0], acc[mt][nt][1]);
            *reinterpret_cast<float2*>(Db + (size_t)(row + 8) * ldd + col) =
                make_float2(acc[mt][nt][2], acc[mt][nt][3]);
        }
    }
}

// ---------------------------------------------------------------------------
// Masked softmax over S; reads g_scores (f32), writes split probs (Ph, Pl).
// One warp per (b,l) row.
// ---------------------------------------------------------------------------
__global__ void __launch_bounds__(256) softmax_split(const int* __restrict__ mask)
{
    const int row  = blockIdx.x * 8 + (threadIdx.x >> 5);
    const int lane = threadIdx.x & 31;
    const int b    = row >> 9;

    const float* p  = g_scores + (size_t)row * S_DIM;
    const int* mrow = mask + (size_t)b * S_DIM;

    float4 fv[4];
    float mx = -3e38f;
    #pragma unroll
    for (int c = 0; c < 4; ++c) {
        const int s = c * 128 + lane * 4;
        float4 x = *reinterpret_cast<const float4*>(p + s);
        int4 mm = *reinterpret_cast<const int4*>(mrow + s);
        x.x = (mm.x == 0) ? NEG_INF_F : x.x;
        x.y = (mm.y == 0) ? NEG_INF_F : x.y;
        x.z = (mm.z == 0) ? NEG_INF_F : x.z;
        x.w = (mm.w == 0) ? NEG_INF_F : x.w;
        fv[c] = x;
        mx = fmaxf(mx, fmaxf(fmaxf(x.x, x.y), fmaxf(x.z, x.w)));
    }
    #pragma unroll
    for (int o = 16; o > 0; o >>= 1) mx = fmaxf(mx, __shfl_xor_sync(0xffffffffu, mx, o));

    float sum = 0.0f;
    #pragma unroll
    for (int c = 0; c < 4; ++c) {
        fv[c].x = expf(fv[c].x - mx); fv[c].y = expf(fv[c].y - mx);
        fv[c].z = expf(fv[c].z - mx); fv[c].w = expf(fv[c].w - mx);
        sum += fv[c].x + fv[c].y + fv[c].z + fv[c].w;
    }
    #pragma unroll
    for (int o = 16; o > 0; o >>= 1) sum += __shfl_xor_sync(0xffffffffu, sum, o);

    const float inv = 1.0f / sum;
    #pragma unroll
    for (int c = 0; c < 4; ++c) {
        const int s = c * 128 + lane * 4;
        float v0 = fv[c].x * inv, v1 = fv[c].y * inv, v2 = fv[c].z * inv, v3 = fv[c].w * inv;
        __nv_bfloat16 h0, l0, h1, l1, h2, l2, h3, l3;
        split2(v0, h0, l0); split2(v1, h1, l1); split2(v2, h2, l2); split2(v3, h3, l3);
        __nv_bfloat162* ph = reinterpret_cast<__nv_bfloat162*>(g_Ph + (size_t)row * S_DIM + s);
        __nv_bfloat162* pl = reinterpret_cast<__nv_bfloat162*>(g_Pl + (size_t)row * S_DIM + s);
        ph[0] = __nv_bfloat162{h0, h1}; ph[1] = __nv_bfloat162{h2, h3};
        pl[0] = __nv_bfloat162{l0, l1}; pl[1] = __nv_bfloat162{l2, l3};
    }
}

// ---------------------------------------------------------------------------
// Launch
// ---------------------------------------------------------------------------
extern "C" void kernel_launch(void* const* d_in, const int* in_sizes, int n_in,
                              void* d_out, int out_size)
{
    const float* X    = (const float*)d_in[0];   // [B, S, H]
    const int*   mask = (const int*)  d_in[1];   // [B, S]
    const float* W    = (const float*)d_in[2];   // [L, H]
    float* out = (float*)d_out;                  // [B, L, H]

    cudaFuncSetAttribute(gemm_hmma_x3<true>,  cudaFuncAttributeMaxDynamicSharedMemorySize, GEMM_SMEM);
    cudaFuncSetAttribute(gemm_hmma_x3<false>, cudaFuncAttributeMaxDynamicSharedMemorySize, GEMM_SMEM);

    void *pXh, *pXl, *pWh, *pWl, *pPh, *pPl, *pSc;
    cudaGetSymbolAddress(&pXh, g_Xh); cudaGetSymbolAddress(&pXl, g_Xl);
    cudaGetSymbolAddress(&pWh, g_Wh); cudaGetSymbolAddress(&pWl, g_Wl);
    cudaGetSymbolAddress(&pPh, g_Ph); cudaGetSymbolAddress(&pPl, g_Pl);
    cudaGetSymbolAddress(&pSc, g_scores);

    convert_W<<<(L_DIM * H_DIM) / 1024, 256>>>(W);
    convert_X<<<((size_t)B_DIM * S_DIM * H_DIM) / 1024, 256>>>(X);

    // GEMM1 (NT): scores[b,l,s] = W[l,:] . X[b,s,:]   M=L, N=S, K=H
    gemm_hmma_x3<true><<<dim3(S_DIM / 128, L_DIM / 128, B_DIM), 256, GEMM_SMEM>>>(
        (const __nv_bfloat16*)pWh, (const __nv_bfloat16*)pWl,
        (const __nv_bfloat16*)pXh, (const __nv_bfloat16*)pXl,
        (float*)pSc,
        H_DIM, H_DIM, S_DIM, H_DIM / 64,
        0, (size_t)S_DIM * H_DIM, (size_t)L_DIM * S_DIM);

    softmax_split<<<(B_DIM * L_DIM) / 8, 256>>>(mask);

    // GEMM2 (NN): out[b,l,h] = P[b,l,:] . X[b,:,h]    M=L, N=H, K=S
    gemm_hmma_x3<false><<<dim3(H_DIM / 128, L_DIM / 128, B_DIM), 256, GEMM_SMEM>>>(
        (const __nv_bfloat16*)pPh, (const __nv_bfloat16*)pPl,
        (const __nv_bfloat16*)pXh, (const __nv_bfloat16*)pXl,
        out,
        S_DIM, H_DIM, H_DIM, S_DIM / 64,
        (size_t)L_DIM * S_DIM, (size_t)S_DIM * H_DIM, (size_t)L_DIM * H_DIM);
}